// round 7
// baseline (speedup 1.0000x reference)
#include <cuda_runtime.h>
#include <cuda_bf16.h>
#include <cstdint>

#define BATCH 32
#define CDIM  64
#define HW    4096
#define NPTS  (BATCH * HW)          // 131072
#define KCODES 1024
#define ZQ_ELEMS (NPTS * CDIM)      // 8388608
#define NCHUNK 128
#define BSTR   132                  // u64 stride for B rows
#define ZSTR   132                  // f32 stride for ZS rows
#define EPS_F  6e-5f

// ---------------------------------------------------------------------------
// Device-global scratch (allocation-free rule)
// ---------------------------------------------------------------------------
__device__ float  g_enorm[KCODES];
__device__ double g_part[1024];
// Pre-packed B fragments: [row = kt*4+r][code n], u64 = {b0 = bf16x2(c0,c0+1),
// b1 = bf16x2(c0+8,c0+9)} with c0 = kt*16 + 2r.
__device__ unsigned long long g_ebh2[16 * KCODES];
__device__ unsigned long long g_ebl2[16 * KCODES];

// ---------------------------------------------------------------------------
__device__ __forceinline__ void mma16816(float* d, const uint32_t* a,
                                         uint32_t b0, uint32_t b1) {
    asm volatile(
        "mma.sync.aligned.m16n8k16.row.col.f32.bf16.bf16.f32 "
        "{%0,%1,%2,%3}, {%4,%5,%6,%7}, {%8,%9}, {%0,%1,%2,%3};"
        : "+f"(d[0]), "+f"(d[1]), "+f"(d[2]), "+f"(d[3])
        : "r"(a[0]), "r"(a[1]), "r"(a[2]), "r"(a[3]), "r"(b0), "r"(b1));
}

__device__ __forceinline__ uint32_t pack_bf16x2(float lo, float hi) {
    const uint16_t l = __bfloat16_as_ushort(__float2bfloat16_rn(lo));
    const uint16_t h = __bfloat16_as_ushort(__float2bfloat16_rn(hi));
    return ((uint32_t)h << 16) | l;
}

// ---------------------------------------------------------------------------
// SMEM layout (bytes)
// ---------------------------------------------------------------------------
#define SM_ZN    0                            // 128 f32           (512)
#define SM_KEYS  512                          // 128 u64           (1024)
#define SM_RED   1536                         // 256 double        (2048)
#define SM_EN    3584                         // 1024 f32          (4096)
#define SM_TOP   7680                         // u64[128][4][2]    (8192)
#define SM_CNT   15872                        // int[128]... u8[512]
#define SM_ZS    16384                        // f32[64][ZSTR]     (33792)
#define SM_B_H   50176                        // u64[16][BSTR]     (16896)
#define SM_B_L   67072                        //                   (16896)
#define SM_TOTAL 83968

// ---------------------------------------------------------------------------
// Kernel 0: emb prep — enorm + packed bf16 hi/lo B-fragment images
// ---------------------------------------------------------------------------
__global__ void prep_kernel(const float* __restrict__ emb) {
    const int n = blockIdx.x * 256 + threadIdx.x;
    if (n >= KCODES) return;
    float e[CDIM];
    float acc = 0.0f;
#pragma unroll
    for (int c = 0; c < CDIM; ++c) {
        e[c] = emb[(size_t)n * CDIM + c];
        acc = __fadd_rn(acc, __fmul_rn(e[c], e[c]));
    }
    g_enorm[n] = acc;

    float eh[CDIM], el[CDIM];
#pragma unroll
    for (int c = 0; c < CDIM; ++c) {
        const float h = __bfloat162float(__float2bfloat16_rn(e[c]));
        eh[c] = h;
        el[c] = __fsub_rn(e[c], h);
    }
#pragma unroll
    for (int kt = 0; kt < 4; ++kt)
#pragma unroll
        for (int r = 0; r < 4; ++r) {
            const int c0 = kt * 16 + 2 * r;
            const int row = kt * 4 + r;
            unsigned long long vh =
                ((unsigned long long)pack_bf16x2(eh[c0 + 8], eh[c0 + 9]) << 32) |
                pack_bf16x2(eh[c0], eh[c0 + 1]);
            unsigned long long vl =
                ((unsigned long long)pack_bf16x2(el[c0 + 8], el[c0 + 9]) << 32) |
                pack_bf16x2(el[c0], el[c0 + 1]);
            g_ebh2[row * KCODES + n] = vh;
            g_ebl2[row * KCODES + n] = vl;
        }
}

// ---------------------------------------------------------------------------
// Kernel 1: mma.sync GEMM scan + exact-rescue argmin + gather + loss
// ---------------------------------------------------------------------------
__global__ __launch_bounds__(256, 2)
void vq_main_kernel(const float* __restrict__ z, const float* __restrict__ emb,
                    float* __restrict__ out) {
    extern __shared__ char smem[];
    float*  zn_s  = (float*)(smem + SM_ZN);
    unsigned long long* keys = (unsigned long long*)(smem + SM_KEYS);
    double* red   = (double*)(smem + SM_RED);
    float*  en_s  = (float*)(smem + SM_EN);
    unsigned long long* top = (unsigned long long*)(smem + SM_TOP);
    unsigned char* cnt_s = (unsigned char*)(smem + SM_CNT);
    float*  zs    = (float*)(smem + SM_ZS);

    const int tid  = threadIdx.x;
    const int wid  = tid >> 5;
    const int lane = tid & 31;
    const int g    = lane >> 2;
    const int j    = lane & 3;

    const int m0  = blockIdx.x * 128;
    const int b   = m0 >> 12;
    const int hw0 = m0 & 4095;
    const size_t zb = (size_t)b * (CDIM * HW);

    // --- Stage exact z tile into ZS [c][p] ---
#pragma unroll
    for (int p8 = 0; p8 < 8; ++p8) {
        const int idx = p8 * 256 + tid;
        const int c  = idx >> 5;
        const int g4 = idx & 31;
        const float4 v = *(const float4*)&z[zb + (size_t)c * HW + hw0 + g4 * 4];
        *(float4*)&zs[c * ZSTR + g4 * 4] = v;
    }
    __syncthreads();

    // --- znorm (exact sequential) / enorm copy ---
    if (tid < 128) {
        float acc = 0.0f;
#pragma unroll
        for (int c = 0; c < CDIM; ++c) {
            const float v = zs[c * ZSTR + tid];
            acc = __fadd_rn(acc, __fmul_rn(v, v));
        }
        zn_s[tid] = acc;
    } else {
        const int i = tid - 128;
        ((float4*)en_s)[i]       = ((const float4*)g_enorm)[i];
        ((float4*)en_s)[i + 128] = ((const float4*)g_enorm)[i + 128];
    }
    __syncthreads();

    // --- Build persistent A fragments from ZS ---
    const int p0 = wid * 16 + g;
    const int p1 = p0 + 8;
    uint32_t Ah[4][4], Al[4][4];
#pragma unroll
    for (int kt = 0; kt < 4; ++kt) {
        const int cA = kt * 16 + 2 * j;
        const int cB = cA + 8;
#pragma unroll
        for (int r = 0; r < 4; ++r) {
            const int cc = (r < 2) ? cA : cB;
            const int pp = (r & 1) ? p1 : p0;
            const float x0 = zs[cc * ZSTR + pp];
            const float x1 = zs[(cc + 1) * ZSTR + pp];
            const float h0 = __bfloat162float(__float2bfloat16_rn(x0));
            const float h1 = __bfloat162float(__float2bfloat16_rn(x1));
            Ah[kt][r] = pack_bf16x2(h0, h1);
            Al[kt][r] = pack_bf16x2(__fsub_rn(x0, h0), __fsub_rn(x1, h1));
        }
    }
    const float zn0 = zn_s[p0];
    const float zn1 = zn_s[p1];

    // per-lane top-2 (+ overcounting candidate counter) for each point row
    uint32_t b0d0 = 0xFFFFFFFFu, b1d0 = 0xFFFFFFFFu;
    uint32_t b0d1 = 0xFFFFFFFFu, b1d1 = 0xFFFFFFFFu;
    int b0i0 = 0, b1i0 = 0, b0i1 = 0, b1i1 = 0;
    int cnt0 = 0, cnt1 = 0;

    const uint2* bh = (const uint2*)(smem + SM_B_H);
    const uint2* bl = (const uint2*)(smem + SM_B_L);

    for (int ch = 0; ch < 8; ++ch) {
        // load B chunk into smem
        {
            const int job  = tid >> 3;
            const int i    = tid & 7;
            const int term = job >> 4;
            const int row  = job & 15;
            const uint4* src = (const uint4*)((term ? g_ebl2 : g_ebh2) +
                                              row * KCODES + ch * NCHUNK);
            uint4* dst = (uint4*)(smem + (term ? SM_B_L : SM_B_H)) + row * (BSTR / 2);
#pragma unroll
            for (int q = 0; q < 8; ++q) dst[q * 8 + i] = src[q * 8 + i];
        }
        __syncthreads();

        for (int nt = 0; nt < 16; nt += 2) {
            float D[6][4];
#pragma unroll
            for (int i = 0; i < 6; ++i)
#pragma unroll
                for (int q = 0; q < 4; ++q) D[i][q] = 0.0f;

            const int n0 = nt * 8 + g;
            const int n1 = n0 + 8;
#pragma unroll
            for (int kt = 0; kt < 4; ++kt) {
                const int rb = (kt * 4 + j) * BSTR;
                const uint2 vh0 = bh[rb + n0];
                const uint2 vh1 = bh[rb + n1];
                const uint2 vl0 = bl[rb + n0];
                const uint2 vl1 = bl[rb + n1];
                mma16816(D[0], Ah[kt], vh0.x, vh0.y);
                mma16816(D[1], Ah[kt], vh1.x, vh1.y);
                mma16816(D[2], Al[kt], vh0.x, vh0.y);
                mma16816(D[3], Al[kt], vh1.x, vh1.y);
                mma16816(D[4], Ah[kt], vl0.x, vl0.y);
                mma16816(D[5], Ah[kt], vl1.x, vl1.y);
            }

#pragma unroll
            for (int t = 0; t < 2; ++t) {
                const int kb = ch * 128 + (nt + t) * 8 + 2 * j;
                const float2 en2 = *(const float2*)&en_s[kb];
                float dot[4];
#pragma unroll
                for (int q = 0; q < 4; ++q)
                    dot[q] = __fadd_rn(__fadd_rn(D[t][q], D[2 + t][q]), D[4 + t][q]);

                const float d00 = __fsub_rn(__fadd_rn(zn0, en2.x), __fadd_rn(dot[0], dot[0]));
                const float d01 = __fsub_rn(__fadd_rn(zn0, en2.y), __fadd_rn(dot[1], dot[1]));
                const float d10 = __fsub_rn(__fadd_rn(zn1, en2.x), __fadd_rn(dot[2], dot[2]));
                const float d11 = __fsub_rn(__fadd_rn(zn1, en2.y), __fadd_rn(dot[3], dot[3]));

#define UPD(dv, ki, B0D, B0I, B1D, B1I, CNT)                                   \
                { const uint32_t u = __float_as_uint(dv);                      \
                  if (u < B0D) { B1D = B0D; B1I = B0I; B0D = u; B0I = (ki); }  \
                  else if (u < B1D) { B1D = u; B1I = (ki); }                   \
                  if ((dv) <= __fadd_rn(__uint_as_float(B0D), EPS_F)) ++CNT; }

                UPD(d00, kb,     b0d0, b0i0, b1d0, b1i0, cnt0);
                UPD(d01, kb + 1, b0d0, b0i0, b1d0, b1i0, cnt0);
                UPD(d10, kb,     b0d1, b0i1, b1d1, b1i1, cnt1);
                UPD(d11, kb + 1, b0d1, b0i1, b1d1, b1i1, cnt1);
#undef UPD
            }
        }
        __syncthreads();
    }

    // --- publish per-lane top-2 + counts ---
    top[(p0 * 4 + j) * 2 + 0] = ((unsigned long long)b0d0 << 32) | (unsigned int)b0i0;
    top[(p0 * 4 + j) * 2 + 1] = ((unsigned long long)b1d0 << 32) | (unsigned int)b1i0;
    top[(p1 * 4 + j) * 2 + 0] = ((unsigned long long)b0d1 << 32) | (unsigned int)b0i1;
    top[(p1 * 4 + j) * 2 + 1] = ((unsigned long long)b1d1 << 32) | (unsigned int)b1i1;
    cnt_s[p0 * 4 + j] = (unsigned char)(cnt0 > 250 ? 250 : cnt0);
    cnt_s[p1 * 4 + j] = (unsigned char)(cnt1 > 250 ? 250 : cnt1);
    __syncthreads();

    // --- rescue: exact fp32 re-check where MMA precision could matter ---
    if (tid < 128) {
        const int p = tid;
        unsigned long long kk[8];
#pragma unroll
        for (int l = 0; l < 4; ++l) {
            kk[2 * l]     = top[(p * 4 + l) * 2];
            kk[2 * l + 1] = top[(p * 4 + l) * 2 + 1];
        }
        unsigned long long best = kk[0];
#pragma unroll
        for (int i = 1; i < 8; ++i) if (kk[i] < best) best = kk[i];

        int cmax = 0;
#pragma unroll
        for (int l = 0; l < 4; ++l) {
            const int cv = cnt_s[p * 4 + l];
            if (cv > cmax) cmax = cv;
        }

        const float bd  = __uint_as_float((uint32_t)(best >> 32));
        const float thr = __fadd_rn(bd, EPS_F);
        bool need = false;
#pragma unroll
        for (int i = 0; i < 8; ++i) {
            const float di = __uint_as_float((uint32_t)(kk[i] >> 32));
            if (kk[i] != best && di <= thr) need = true;
        }

        const float znp = zn_s[p];
        if (cmax >= 3) {
            // ultra-rare: full exact scan of all 1024 codes
            unsigned long long nb = 0xFFFFFFFFFFFFFFFFull;
            for (int k = 0; k < KCODES; ++k) {
                float dot = 0.0f;
#pragma unroll
                for (int c = 0; c < CDIM; ++c)
                    dot = __fmaf_rn(zs[c * ZSTR + p], emb[(size_t)k * CDIM + c], dot);
                const float dd = __fsub_rn(__fadd_rn(znp, en_s[k]), __fadd_rn(dot, dot));
                const unsigned long long key =
                    ((unsigned long long)__float_as_uint(dd) << 32) | (unsigned int)k;
                if (key < nb) nb = key;
            }
            best = nb;
        } else if (need) {
            unsigned long long nb = 0xFFFFFFFFFFFFFFFFull;
#pragma unroll
            for (int i = 0; i < 8; ++i) {
                const float di = __uint_as_float((uint32_t)(kk[i] >> 32));
                if (di <= thr) {
                    const int k = (int)(kk[i] & 0xFFFFFFFFull);
                    float dot = 0.0f;
#pragma unroll
                    for (int c = 0; c < CDIM; ++c)
                        dot = __fmaf_rn(zs[c * ZSTR + p], emb[(size_t)k * CDIM + c], dot);
                    const float dd = __fsub_rn(__fadd_rn(znp, en_s[k]), __fadd_rn(dot, dot));
                    const unsigned long long key =
                        ((unsigned long long)__float_as_uint(dd) << 32) | (unsigned int)k;
                    if (key < nb) nb = key;
                }
            }
            best = nb;
        }
        keys[p] = best;
    }
    __syncthreads();

    // --- gather + straight-through output + loss partials ---
    double acc = 0.0;
    {
        const int p   = tid & 127;
        const int ch2 = tid >> 7;
        const int idx = (int)(keys[p] & 0xFFFFFFFFull);
        const float* erow = emb + (size_t)idx * CDIM + ch2 * 32;
        const size_t obase = zb + hw0 + p;
#pragma unroll
        for (int c4 = 0; c4 < 8; ++c4) {
            const float4 e4 = *(const float4*)&erow[c4 * 4];
            const float ee[4] = {e4.x, e4.y, e4.z, e4.w};
#pragma unroll
            for (int q = 0; q < 4; ++q) {
                const int c = ch2 * 32 + c4 * 4 + q;
                const size_t off = obase + (size_t)c * HW;
                const float zv = zs[c * ZSTR + p];
                const float dd = __fsub_rn(ee[q], zv);
                out[off] = __fadd_rn(zv, dd);            // fl(z + (z_q - z))
                acc += (double)__fmul_rn(dd, dd);
            }
        }
    }

    red[tid] = acc;
    __syncthreads();
#pragma unroll
    for (int s = 128; s >= 1; s >>= 1) {
        if (tid < s) red[tid] += red[tid + s];
        __syncthreads();
    }
    if (tid == 0) g_part[blockIdx.x] = red[0];
}

// ---------------------------------------------------------------------------
__global__ void loss_kernel(float* __restrict__ out, int out_size) {
    __shared__ double red[256];
    const int tid = threadIdx.x;
    red[tid] = g_part[tid] + g_part[tid + 256] + g_part[tid + 512] + g_part[tid + 768];
    __syncthreads();
#pragma unroll
    for (int s = 128; s >= 1; s >>= 1) {
        if (tid < s) red[tid] += red[tid + s];
        __syncthreads();
    }
    if (tid == 0) {
        const double mean = red[0] / (double)ZQ_ELEMS;
        const float mf = (float)mean;
        out[out_size - 1] = __fadd_rn(mf, __fmul_rn(0.5f, mf));
    }
}

// ---------------------------------------------------------------------------
extern "C" void kernel_launch(void* const* d_in, const int* in_sizes, int n_in,
                              void* d_out, int out_size) {
    const float* z   = (const float*)d_in[0];
    const float* emb = (const float*)d_in[1];
    float* out = (float*)d_out;

    cudaFuncSetAttribute(vq_main_kernel,
                         cudaFuncAttributeMaxDynamicSharedMemorySize, SM_TOTAL);

    prep_kernel<<<4, 256>>>(emb);
    vq_main_kernel<<<NPTS / 128, 256, SM_TOTAL>>>(z, emb, out);
    loss_kernel<<<1, 256>>>(out, out_size);
}

// round 8
// speedup vs baseline: 1.8597x; 1.8597x over previous
#include <cuda_runtime.h>
#include <cuda_bf16.h>
#include <cstdint>

#define BATCH 32
#define CDIM  64
#define HW    4096
#define NPTS  (BATCH * HW)          // 131072
#define KCODES 1024
#define ZQ_ELEMS (NPTS * CDIM)      // 8388608
#define NCHUNK 128
#define BSTR   132                  // u64 stride for B rows
#define ZSTR   132                  // f32 stride for ZS rows
#define EPS_F  6e-5f

// ---------------------------------------------------------------------------
// Device-global scratch (allocation-free rule)
// ---------------------------------------------------------------------------
__device__ float  g_enorm[KCODES];
__device__ double g_part[1024];
// Pre-packed B fragments: [row = kt*4+r][code n], u64 = {b0 = bf16x2(c0,c0+1),
// b1 = bf16x2(c0+8,c0+9)} with c0 = kt*16 + 2r.
__device__ unsigned long long g_ebh2[16 * KCODES];
__device__ unsigned long long g_ebl2[16 * KCODES];

// ---------------------------------------------------------------------------
__device__ __forceinline__ void mma16816(float* d, const uint32_t* a,
                                         uint32_t b0, uint32_t b1) {
    asm volatile(
        "mma.sync.aligned.m16n8k16.row.col.f32.bf16.bf16.f32 "
        "{%0,%1,%2,%3}, {%4,%5,%6,%7}, {%8,%9}, {%0,%1,%2,%3};"
        : "+f"(d[0]), "+f"(d[1]), "+f"(d[2]), "+f"(d[3])
        : "r"(a[0]), "r"(a[1]), "r"(a[2]), "r"(a[3]), "r"(b0), "r"(b1));
}

__device__ __forceinline__ uint32_t pack_bf16x2(float lo, float hi) {
    const uint16_t l = __bfloat16_as_ushort(__float2bfloat16_rn(lo));
    const uint16_t h = __bfloat16_as_ushort(__float2bfloat16_rn(hi));
    return ((uint32_t)h << 16) | l;
}

// ---------------------------------------------------------------------------
// SMEM layout (bytes)
// ---------------------------------------------------------------------------
#define SM_ZN    0                            // 128 f32           (512)
#define SM_KEYS  512                          // 128 u64           (1024)
#define SM_RED   1536                         // 256 double        (2048)
#define SM_EN    3584                         // 1024 f32          (4096)
#define SM_TOP   7680                         // u64[128][4][2]    (8192)
#define SM_ZS    16384                        // f32[64][ZSTR]     (33792)
#define SM_B_H   50176                        // u64[16][BSTR]     (16896)
#define SM_B_L   67072                        //                   (16896)
#define SM_TOTAL 83968

// ---------------------------------------------------------------------------
// Kernel 0: emb prep — enorm + packed bf16 hi/lo B-fragment images
// ---------------------------------------------------------------------------
__global__ void prep_kernel(const float* __restrict__ emb) {
    const int n = blockIdx.x * 256 + threadIdx.x;
    if (n >= KCODES) return;
    float e[CDIM];
    float acc = 0.0f;
#pragma unroll
    for (int c = 0; c < CDIM; ++c) {
        e[c] = emb[(size_t)n * CDIM + c];
        acc = __fadd_rn(acc, __fmul_rn(e[c], e[c]));
    }
    g_enorm[n] = acc;

    float eh[CDIM], el[CDIM];
#pragma unroll
    for (int c = 0; c < CDIM; ++c) {
        const float h = __bfloat162float(__float2bfloat16_rn(e[c]));
        eh[c] = h;
        el[c] = __fsub_rn(e[c], h);
    }
#pragma unroll
    for (int kt = 0; kt < 4; ++kt)
#pragma unroll
        for (int r = 0; r < 4; ++r) {
            const int c0 = kt * 16 + 2 * r;
            const int row = kt * 4 + r;
            unsigned long long vh =
                ((unsigned long long)pack_bf16x2(eh[c0 + 8], eh[c0 + 9]) << 32) |
                pack_bf16x2(eh[c0], eh[c0 + 1]);
            unsigned long long vl =
                ((unsigned long long)pack_bf16x2(el[c0 + 8], el[c0 + 9]) << 32) |
                pack_bf16x2(el[c0], el[c0 + 1]);
            g_ebh2[row * KCODES + n] = vh;
            g_ebl2[row * KCODES + n] = vl;
        }
}

// ---------------------------------------------------------------------------
// Kernel 1: mma.sync GEMM scan + exact-rescue argmin + gather + loss
// ---------------------------------------------------------------------------
__global__ __launch_bounds__(256, 2)
void vq_main_kernel(const float* __restrict__ z, const float* __restrict__ emb,
                    float* __restrict__ out) {
    extern __shared__ char smem[];
    float*  zn_s  = (float*)(smem + SM_ZN);
    unsigned long long* keys = (unsigned long long*)(smem + SM_KEYS);
    double* red   = (double*)(smem + SM_RED);
    float*  en_s  = (float*)(smem + SM_EN);
    unsigned long long* top = (unsigned long long*)(smem + SM_TOP);
    float*  zs    = (float*)(smem + SM_ZS);

    const int tid  = threadIdx.x;
    const int wid  = tid >> 5;
    const int lane = tid & 31;
    const int g    = lane >> 2;
    const int j    = lane & 3;

    const int m0  = blockIdx.x * 128;
    const int b   = m0 >> 12;
    const int hw0 = m0 & 4095;
    const size_t zb = (size_t)b * (CDIM * HW);

    // --- Stage exact z tile into ZS [c][p] ---
#pragma unroll
    for (int p8 = 0; p8 < 8; ++p8) {
        const int idx = p8 * 256 + tid;
        const int c  = idx >> 5;
        const int g4 = idx & 31;
        const float4 v = *(const float4*)&z[zb + (size_t)c * HW + hw0 + g4 * 4];
        *(float4*)&zs[c * ZSTR + g4 * 4] = v;
    }
    __syncthreads();

    // --- znorm (exact sequential) / enorm copy ---
    if (tid < 128) {
        float acc = 0.0f;
#pragma unroll
        for (int c = 0; c < CDIM; ++c) {
            const float v = zs[c * ZSTR + tid];
            acc = __fadd_rn(acc, __fmul_rn(v, v));
        }
        zn_s[tid] = acc;
    } else {
        const int i = tid - 128;
        ((float4*)en_s)[i]       = ((const float4*)g_enorm)[i];
        ((float4*)en_s)[i + 128] = ((const float4*)g_enorm)[i + 128];
    }
    __syncthreads();

    // --- Build persistent A fragments from ZS ---
    const int p0 = wid * 16 + g;
    const int p1 = p0 + 8;
    uint32_t Ah[4][4], Al[4][4];
#pragma unroll
    for (int kt = 0; kt < 4; ++kt) {
        const int cA = kt * 16 + 2 * j;
        const int cB = cA + 8;
#pragma unroll
        for (int r = 0; r < 4; ++r) {
            const int cc = (r < 2) ? cA : cB;
            const int pp = (r & 1) ? p1 : p0;
            const float x0 = zs[cc * ZSTR + pp];
            const float x1 = zs[(cc + 1) * ZSTR + pp];
            const float h0 = __bfloat162float(__float2bfloat16_rn(x0));
            const float h1 = __bfloat162float(__float2bfloat16_rn(x1));
            Ah[kt][r] = pack_bf16x2(h0, h1);
            Al[kt][r] = pack_bf16x2(__fsub_rn(x0, h0), __fsub_rn(x1, h1));
        }
    }
    const float zn0 = zn_s[p0];
    const float zn1 = zn_s[p1];

    // per-lane top-2 for each of the thread's two point rows
    uint32_t b0d0 = 0xFFFFFFFFu, b1d0 = 0xFFFFFFFFu;
    uint32_t b0d1 = 0xFFFFFFFFu, b1d1 = 0xFFFFFFFFu;
    int b0i0 = 0, b1i0 = 0, b0i1 = 0, b1i1 = 0;

    const uint2* bh = (const uint2*)(smem + SM_B_H);
    const uint2* bl = (const uint2*)(smem + SM_B_L);

    for (int ch = 0; ch < 8; ++ch) {
        // load B chunk into smem
        {
            const int job  = tid >> 3;
            const int i    = tid & 7;
            const int term = job >> 4;
            const int row  = job & 15;
            const uint4* src = (const uint4*)((term ? g_ebl2 : g_ebh2) +
                                              row * KCODES + ch * NCHUNK);
            uint4* dst = (uint4*)(smem + (term ? SM_B_L : SM_B_H)) + row * (BSTR / 2);
#pragma unroll
            for (int q = 0; q < 8; ++q) dst[q * 8 + i] = src[q * 8 + i];
        }
        __syncthreads();

        for (int nt = 0; nt < 16; nt += 2) {
            float D[6][4];
#pragma unroll
            for (int i = 0; i < 6; ++i)
#pragma unroll
                for (int q = 0; q < 4; ++q) D[i][q] = 0.0f;

            const int n0 = nt * 8 + g;
            const int n1 = n0 + 8;
#pragma unroll
            for (int kt = 0; kt < 4; ++kt) {
                const int rb = (kt * 4 + j) * BSTR;
                const uint2 vh0 = bh[rb + n0];
                const uint2 vh1 = bh[rb + n1];
                const uint2 vl0 = bl[rb + n0];
                const uint2 vl1 = bl[rb + n1];
                mma16816(D[0], Ah[kt], vh0.x, vh0.y);
                mma16816(D[1], Ah[kt], vh1.x, vh1.y);
                mma16816(D[2], Al[kt], vh0.x, vh0.y);
                mma16816(D[3], Al[kt], vh1.x, vh1.y);
                mma16816(D[4], Ah[kt], vl0.x, vl0.y);
                mma16816(D[5], Ah[kt], vl1.x, vl1.y);
            }

#pragma unroll
            for (int t = 0; t < 2; ++t) {
                const int kb = ch * 128 + (nt + t) * 8 + 2 * j;
                const float2 en2 = *(const float2*)&en_s[kb];
                float dot[4];
#pragma unroll
                for (int q = 0; q < 4; ++q)
                    dot[q] = __fadd_rn(__fadd_rn(D[t][q], D[2 + t][q]), D[4 + t][q]);

                const float d00 = __fsub_rn(__fadd_rn(zn0, en2.x), __fadd_rn(dot[0], dot[0]));
                const float d01 = __fsub_rn(__fadd_rn(zn0, en2.y), __fadd_rn(dot[1], dot[1]));
                const float d10 = __fsub_rn(__fadd_rn(zn1, en2.x), __fadd_rn(dot[2], dot[2]));
                const float d11 = __fsub_rn(__fadd_rn(zn1, en2.y), __fadd_rn(dot[3], dot[3]));

#define UPD(dv, ki, B0D, B0I, B1D, B1I)                                        \
                { const uint32_t u = __float_as_uint(dv);                      \
                  if (u < B0D) { B1D = B0D; B1I = B0I; B0D = u; B0I = (ki); }  \
                  else if (u < B1D) { B1D = u; B1I = (ki); } }

                UPD(d00, kb,     b0d0, b0i0, b1d0, b1i0);
                UPD(d01, kb + 1, b0d0, b0i0, b1d0, b1i0);
                UPD(d10, kb,     b0d1, b0i1, b1d1, b1i1);
                UPD(d11, kb + 1, b0d1, b0i1, b1d1, b1i1);
#undef UPD
            }
        }
        __syncthreads();
    }

    // --- publish per-lane top-2 ---
    top[(p0 * 4 + j) * 2 + 0] = ((unsigned long long)b0d0 << 32) | (unsigned int)b0i0;
    top[(p0 * 4 + j) * 2 + 1] = ((unsigned long long)b1d0 << 32) | (unsigned int)b1i0;
    top[(p1 * 4 + j) * 2 + 0] = ((unsigned long long)b0d1 << 32) | (unsigned int)b0i1;
    top[(p1 * 4 + j) * 2 + 1] = ((unsigned long long)b1d1 << 32) | (unsigned int)b1i1;
    __syncthreads();

    // --- rescue: exact fp32 re-check where MMA precision could matter ---
    if (tid < 128) {
        const int p = tid;
        unsigned long long kk[8];
#pragma unroll
        for (int l = 0; l < 4; ++l) {
            kk[2 * l]     = top[(p * 4 + l) * 2];
            kk[2 * l + 1] = top[(p * 4 + l) * 2 + 1];
        }
        unsigned long long best = kk[0];
#pragma unroll
        for (int i = 1; i < 8; ++i) if (kk[i] < best) best = kk[i];

        const float bd  = __uint_as_float((uint32_t)(best >> 32));
        const float thr = __fadd_rn(bd, EPS_F);

        // A lane can hide a 3rd in-window candidate only if its 2nd-best is
        // itself in-window (lane lists are sorted).
        bool full = false, need = false;
#pragma unroll
        for (int l = 0; l < 4; ++l) {
            const float d2 = __uint_as_float((uint32_t)(kk[2 * l + 1] >> 32));
            if (d2 <= thr) full = true;
        }
#pragma unroll
        for (int i = 0; i < 8; ++i) {
            const float di = __uint_as_float((uint32_t)(kk[i] >> 32));
            if (kk[i] != best && di <= thr) need = true;
        }

        const float znp = zn_s[p];
        if (full) {
            // rare: full exact scan of all 1024 codes
            unsigned long long nb = 0xFFFFFFFFFFFFFFFFull;
            for (int k = 0; k < KCODES; ++k) {
                float dot = 0.0f;
#pragma unroll
                for (int c = 0; c < CDIM; ++c)
                    dot = __fmaf_rn(zs[c * ZSTR + p], emb[(size_t)k * CDIM + c], dot);
                const float dd = __fsub_rn(__fadd_rn(znp, en_s[k]), __fadd_rn(dot, dot));
                const unsigned long long key =
                    ((unsigned long long)__float_as_uint(dd) << 32) | (unsigned int)k;
                if (key < nb) nb = key;
            }
            best = nb;
        } else if (need) {
            unsigned long long nb = 0xFFFFFFFFFFFFFFFFull;
#pragma unroll
            for (int i = 0; i < 8; ++i) {
                const float di = __uint_as_float((uint32_t)(kk[i] >> 32));
                if (di <= thr) {
                    const int k = (int)(kk[i] & 0xFFFFFFFFull);
                    float dot = 0.0f;
#pragma unroll
                    for (int c = 0; c < CDIM; ++c)
                        dot = __fmaf_rn(zs[c * ZSTR + p], emb[(size_t)k * CDIM + c], dot);
                    const float dd = __fsub_rn(__fadd_rn(znp, en_s[k]), __fadd_rn(dot, dot));
                    const unsigned long long key =
                        ((unsigned long long)__float_as_uint(dd) << 32) | (unsigned int)k;
                    if (key < nb) nb = key;
                }
            }
            best = nb;
        }
        keys[p] = best;
    }
    __syncthreads();

    // --- gather + straight-through output + loss partials ---
    double acc = 0.0;
    {
        const int p   = tid & 127;
        const int ch2 = tid >> 7;
        const int idx = (int)(keys[p] & 0xFFFFFFFFull);
        const float* erow = emb + (size_t)idx * CDIM + ch2 * 32;
        const size_t obase = zb + hw0 + p;
#pragma unroll
        for (int c4 = 0; c4 < 8; ++c4) {
            const float4 e4 = *(const float4*)&erow[c4 * 4];
            const float ee[4] = {e4.x, e4.y, e4.z, e4.w};
#pragma unroll
            for (int q = 0; q < 4; ++q) {
                const int c = ch2 * 32 + c4 * 4 + q;
                const size_t off = obase + (size_t)c * HW;
                const float zv = zs[c * ZSTR + p];
                const float dd = __fsub_rn(ee[q], zv);
                out[off] = __fadd_rn(zv, dd);            // fl(z + (z_q - z))
                acc += (double)__fmul_rn(dd, dd);
            }
        }
    }

    red[tid] = acc;
    __syncthreads();
#pragma unroll
    for (int s = 128; s >= 1; s >>= 1) {
        if (tid < s) red[tid] += red[tid + s];
        __syncthreads();
    }
    if (tid == 0) g_part[blockIdx.x] = red[0];
}

// ---------------------------------------------------------------------------
__global__ void loss_kernel(float* __restrict__ out, int out_size) {
    __shared__ double red[256];
    const int tid = threadIdx.x;
    red[tid] = g_part[tid] + g_part[tid + 256] + g_part[tid + 512] + g_part[tid + 768];
    __syncthreads();
#pragma unroll
    for (int s = 128; s >= 1; s >>= 1) {
        if (tid < s) red[tid] += red[tid + s];
        __syncthreads();
    }
    if (tid == 0) {
        const double mean = red[0] / (double)ZQ_ELEMS;
        const float mf = (float)mean;
        out[out_size - 1] = __fadd_rn(mf, __fmul_rn(0.5f, mf));
    }
}

// ---------------------------------------------------------------------------
extern "C" void kernel_launch(void* const* d_in, const int* in_sizes, int n_in,
                              void* d_out, int out_size) {
    const float* z   = (const float*)d_in[0];
    const float* emb = (const float*)d_in[1];
    float* out = (float*)d_out;

    cudaFuncSetAttribute(vq_main_kernel,
                         cudaFuncAttributeMaxDynamicSharedMemorySize, SM_TOTAL);

    prep_kernel<<<4, 256>>>(emb);
    vq_main_kernel<<<NPTS / 128, 256, SM_TOTAL>>>(z, emb, out);
    loss_kernel<<<1, 256>>>(out, out_size);
}

// round 10
// speedup vs baseline: 5.3418x; 2.8724x over previous
#include <cuda_runtime.h>
#include <cuda_bf16.h>
#include <cstdint>

#define BATCH 32
#define CDIM  64
#define HW    4096
#define NPTS  (BATCH * HW)          // 131072
#define KCODES 1024
#define ZQ_ELEMS (NPTS * CDIM)      // 8388608
#define NCHUNK 128
#define BSTR   132                  // u64 stride for B rows
#define ZSTR   132                  // f32 stride for ZS rows
#define EPS_F  6e-5f

// ---------------------------------------------------------------------------
// Device-global scratch (allocation-free rule)
// ---------------------------------------------------------------------------
__device__ float  g_enorm[KCODES];
__device__ double g_part[1024];
// Pre-packed B fragments: [row = kt*4+r][code n], u64 = {b0 = bf16x2(c0,c0+1),
// b1 = bf16x2(c0+8,c0+9)} with c0 = kt*16 + 2r.
__device__ unsigned long long g_ebh2[16 * KCODES];
__device__ unsigned long long g_ebl2[16 * KCODES];

// ---------------------------------------------------------------------------
__device__ __forceinline__ void mma16816(float* d, const uint32_t* a,
                                         uint32_t b0, uint32_t b1) {
    asm volatile(
        "mma.sync.aligned.m16n8k16.row.col.f32.bf16.bf16.f32 "
        "{%0,%1,%2,%3}, {%4,%5,%6,%7}, {%8,%9}, {%0,%1,%2,%3};"
        : "+f"(d[0]), "+f"(d[1]), "+f"(d[2]), "+f"(d[3])
        : "r"(a[0]), "r"(a[1]), "r"(a[2]), "r"(a[3]), "r"(b0), "r"(b1));
}

__device__ __forceinline__ uint32_t pack_bf16x2(float lo, float hi) {
    const uint16_t l = __bfloat16_as_ushort(__float2bfloat16_rn(lo));
    const uint16_t h = __bfloat16_as_ushort(__float2bfloat16_rn(hi));
    return ((uint32_t)h << 16) | l;
}

// ---------------------------------------------------------------------------
// SMEM layout (bytes)
// ---------------------------------------------------------------------------
#define SM_ZN    0                            // 128 f32           (512)
#define SM_KEYS  512                          // 128 u64           (1024)
#define SM_RED   1536                         // 256 double (2048); doubles as
                                              // flag_cnt/list during rescue
#define SM_EN    3584                         // 1024 f32          (4096)
#define SM_TOP   7680                         // u64[128][4][2]    (8192)
#define SM_ZS    16384                        // f32[64][ZSTR]     (33792)
#define SM_B_H   50176                        // u64[16][BSTR]     (16896)
#define SM_B_L   67072                        //                   (16896)
#define SM_TOTAL 83968

// ---------------------------------------------------------------------------
// Kernel 0: emb prep — enorm + packed bf16 hi/lo B-fragment images
// ---------------------------------------------------------------------------
__global__ void prep_kernel(const float* __restrict__ emb) {
    const int n = blockIdx.x * 256 + threadIdx.x;
    if (n >= KCODES) return;
    float acc = 0.0f;
#pragma unroll
    for (int kt = 0; kt < 4; ++kt) {
        float e[16];
#pragma unroll
        for (int i = 0; i < 4; ++i) {
            const float4 v = *(const float4*)&emb[(size_t)n * CDIM + kt * 16 + i * 4];
            e[i * 4 + 0] = v.x; e[i * 4 + 1] = v.y;
            e[i * 4 + 2] = v.z; e[i * 4 + 3] = v.w;
        }
#pragma unroll
        for (int i = 0; i < 16; ++i)
            acc = __fadd_rn(acc, __fmul_rn(e[i], e[i]));
        float eh[16], el[16];
#pragma unroll
        for (int i = 0; i < 16; ++i) {
            eh[i] = __bfloat162float(__float2bfloat16_rn(e[i]));
            el[i] = __fsub_rn(e[i], eh[i]);
        }
#pragma unroll
        for (int r = 0; r < 4; ++r) {
            const int c0 = 2 * r;
            const int row = kt * 4 + r;
            unsigned long long vh =
                ((unsigned long long)pack_bf16x2(eh[c0 + 8], eh[c0 + 9]) << 32) |
                pack_bf16x2(eh[c0], eh[c0 + 1]);
            unsigned long long vl =
                ((unsigned long long)pack_bf16x2(el[c0 + 8], el[c0 + 9]) << 32) |
                pack_bf16x2(el[c0], el[c0 + 1]);
            g_ebh2[row * KCODES + n] = vh;
            g_ebl2[row * KCODES + n] = vl;
        }
    }
    g_enorm[n] = acc;
}

// ---------------------------------------------------------------------------
// Kernel 1: mma.sync GEMM scan + exact-rescue argmin + gather + loss
// ---------------------------------------------------------------------------
__global__ __launch_bounds__(256, 2)
void vq_main_kernel(const float* __restrict__ z, const float* __restrict__ emb,
                    float* __restrict__ out) {
    extern __shared__ char smem[];
    float*  zn_s  = (float*)(smem + SM_ZN);
    unsigned long long* keys = (unsigned long long*)(smem + SM_KEYS);
    double* red   = (double*)(smem + SM_RED);
    int*    flag_cnt  = (int*)(smem + SM_RED);        // overlaps red (used earlier)
    int*    flag_list = (int*)(smem + SM_RED + 4);
    float*  en_s  = (float*)(smem + SM_EN);
    unsigned long long* top = (unsigned long long*)(smem + SM_TOP);
    float*  zs    = (float*)(smem + SM_ZS);

    const int tid  = threadIdx.x;
    const int wid  = tid >> 5;
    const int lane = tid & 31;
    const int g    = lane >> 2;
    const int j    = lane & 3;

    const int m0  = blockIdx.x * 128;
    const int b   = m0 >> 12;
    const int hw0 = m0 & 4095;
    const size_t zb = (size_t)b * (CDIM * HW);

    if (tid == 0) *flag_cnt = 0;

    // --- Stage exact z tile into ZS [c][p] ---
#pragma unroll
    for (int p8 = 0; p8 < 8; ++p8) {
        const int idx = p8 * 256 + tid;
        const int c  = idx >> 5;
        const int g4 = idx & 31;
        const float4 v = *(const float4*)&z[zb + (size_t)c * HW + hw0 + g4 * 4];
        *(float4*)&zs[c * ZSTR + g4 * 4] = v;
    }
    __syncthreads();

    // --- znorm (exact sequential) / enorm copy ---
    if (tid < 128) {
        float acc = 0.0f;
#pragma unroll
        for (int c = 0; c < CDIM; ++c) {
            const float v = zs[c * ZSTR + tid];
            acc = __fadd_rn(acc, __fmul_rn(v, v));
        }
        zn_s[tid] = acc;
    } else {
        const int i = tid - 128;
        ((float4*)en_s)[i]       = ((const float4*)g_enorm)[i];
        ((float4*)en_s)[i + 128] = ((const float4*)g_enorm)[i + 128];
    }
    __syncthreads();

    // --- Build persistent A fragments from ZS ---
    const int p0 = wid * 16 + g;
    const int p1 = p0 + 8;
    uint32_t Ah[4][4], Al[4][4];
#pragma unroll
    for (int kt = 0; kt < 4; ++kt) {
        const int cA = kt * 16 + 2 * j;
        const int cB = cA + 8;
#pragma unroll
        for (int r = 0; r < 4; ++r) {
            const int cc = (r < 2) ? cA : cB;
            const int pp = (r & 1) ? p1 : p0;
            const float x0 = zs[cc * ZSTR + pp];
            const float x1 = zs[(cc + 1) * ZSTR + pp];
            const float h0 = __bfloat162float(__float2bfloat16_rn(x0));
            const float h1 = __bfloat162float(__float2bfloat16_rn(x1));
            Ah[kt][r] = pack_bf16x2(h0, h1);
            Al[kt][r] = pack_bf16x2(__fsub_rn(x0, h0), __fsub_rn(x1, h1));
        }
    }
    const float zn0 = zn_s[p0];
    const float zn1 = zn_s[p1];

    // per-lane top-2 for each of the thread's two point rows
    uint32_t b0d0 = 0xFFFFFFFFu, b1d0 = 0xFFFFFFFFu;
    uint32_t b0d1 = 0xFFFFFFFFu, b1d1 = 0xFFFFFFFFu;
    int b0i0 = 0, b1i0 = 0, b0i1 = 0, b1i1 = 0;

    const uint2* bh = (const uint2*)(smem + SM_B_H);
    const uint2* bl = (const uint2*)(smem + SM_B_L);

    for (int ch = 0; ch < 8; ++ch) {
        // load B chunk into smem
        {
            const int job  = tid >> 3;
            const int i    = tid & 7;
            const int term = job >> 4;
            const int row  = job & 15;
            const uint4* src = (const uint4*)((term ? g_ebl2 : g_ebh2) +
                                              row * KCODES + ch * NCHUNK);
            uint4* dst = (uint4*)(smem + (term ? SM_B_L : SM_B_H)) + row * (BSTR / 2);
#pragma unroll
            for (int q = 0; q < 8; ++q) dst[q * 8 + i] = src[q * 8 + i];
        }
        __syncthreads();

        for (int nt = 0; nt < 16; nt += 2) {
            float D[6][4];
#pragma unroll
            for (int i = 0; i < 6; ++i)
#pragma unroll
                for (int q = 0; q < 4; ++q) D[i][q] = 0.0f;

            const int n0 = nt * 8 + g;
            const int n1 = n0 + 8;
#pragma unroll
            for (int kt = 0; kt < 4; ++kt) {
                const int rb = (kt * 4 + j) * BSTR;
                const uint2 vh0 = bh[rb + n0];
                const uint2 vh1 = bh[rb + n1];
                const uint2 vl0 = bl[rb + n0];
                const uint2 vl1 = bl[rb + n1];
                mma16816(D[0], Ah[kt], vh0.x, vh0.y);
                mma16816(D[1], Ah[kt], vh1.x, vh1.y);
                mma16816(D[2], Al[kt], vh0.x, vh0.y);
                mma16816(D[3], Al[kt], vh1.x, vh1.y);
                mma16816(D[4], Ah[kt], vl0.x, vl0.y);
                mma16816(D[5], Ah[kt], vl1.x, vl1.y);
            }

#pragma unroll
            for (int t = 0; t < 2; ++t) {
                const int kb = ch * 128 + (nt + t) * 8 + 2 * j;
                const float2 en2 = *(const float2*)&en_s[kb];
                float dot[4];
#pragma unroll
                for (int q = 0; q < 4; ++q)
                    dot[q] = __fadd_rn(__fadd_rn(D[t][q], D[2 + t][q]), D[4 + t][q]);

                const float d00 = __fsub_rn(__fadd_rn(zn0, en2.x), __fadd_rn(dot[0], dot[0]));
                const float d01 = __fsub_rn(__fadd_rn(zn0, en2.y), __fadd_rn(dot[1], dot[1]));
                const float d10 = __fsub_rn(__fadd_rn(zn1, en2.x), __fadd_rn(dot[2], dot[2]));
                const float d11 = __fsub_rn(__fadd_rn(zn1, en2.y), __fadd_rn(dot[3], dot[3]));

#define UPD(dv, ki, B0D, B0I, B1D, B1I)                                        \
                { const uint32_t u = __float_as_uint(dv);                      \
                  if (u < B0D) { B1D = B0D; B1I = B0I; B0D = u; B0I = (ki); }  \
                  else if (u < B1D) { B1D = u; B1I = (ki); } }

                UPD(d00, kb,     b0d0, b0i0, b1d0, b1i0);
                UPD(d01, kb + 1, b0d0, b0i0, b1d0, b1i0);
                UPD(d10, kb,     b0d1, b0i1, b1d1, b1i1);
                UPD(d11, kb + 1, b0d1, b0i1, b1d1, b1i1);
#undef UPD
            }
        }
        __syncthreads();
    }

    // --- publish per-lane top-2 ---
    top[(p0 * 4 + j) * 2 + 0] = ((unsigned long long)b0d0 << 32) | (unsigned int)b0i0;
    top[(p0 * 4 + j) * 2 + 1] = ((unsigned long long)b1d0 << 32) | (unsigned int)b1i0;
    top[(p1 * 4 + j) * 2 + 0] = ((unsigned long long)b0d1 << 32) | (unsigned int)b0i1;
    top[(p1 * 4 + j) * 2 + 1] = ((unsigned long long)b1d1 << 32) | (unsigned int)b1i1;
    __syncthreads();

    // --- rescue decision: exact fp32 re-check where MMA precision matters ---
    if (tid < 128) {
        const int p = tid;
        unsigned long long kk[8];
#pragma unroll
        for (int l = 0; l < 4; ++l) {
            kk[2 * l]     = top[(p * 4 + l) * 2];
            kk[2 * l + 1] = top[(p * 4 + l) * 2 + 1];
        }
        unsigned long long best = kk[0];
#pragma unroll
        for (int i = 1; i < 8; ++i) if (kk[i] < best) best = kk[i];

        const float bd  = __uint_as_float((uint32_t)(best >> 32));
        const float thr = __fadd_rn(bd, EPS_F);

        // A lane can hide a 3rd in-window candidate only if its 2nd-best is
        // itself in-window (lane lists are sorted) -> full cooperative scan.
        bool full = false, need = false;
#pragma unroll
        for (int l = 0; l < 4; ++l) {
            const float d2 = __uint_as_float((uint32_t)(kk[2 * l + 1] >> 32));
            if (d2 <= thr) full = true;
        }
#pragma unroll
        for (int i = 0; i < 8; ++i) {
            const float di = __uint_as_float((uint32_t)(kk[i] >> 32));
            if (kk[i] != best && di <= thr) need = true;
        }

        if (full) {
            keys[p] = 0xFFFFFFFFFFFFFFFFull;          // filled cooperatively
            const int slot = atomicAdd(flag_cnt, 1);
            flag_list[slot] = p;
        } else if (need) {
            const float znp = zn_s[p];
            unsigned long long nb = 0xFFFFFFFFFFFFFFFFull;
#pragma unroll
            for (int i = 0; i < 8; ++i) {
                const float di = __uint_as_float((uint32_t)(kk[i] >> 32));
                if (di <= thr) {
                    const int k = (int)(kk[i] & 0xFFFFFFFFull);
                    float dot = 0.0f;
#pragma unroll
                    for (int c = 0; c < CDIM; ++c)
                        dot = __fmaf_rn(zs[c * ZSTR + p], emb[(size_t)k * CDIM + c], dot);
                    const float dd = __fsub_rn(__fadd_rn(znp, en_s[k]), __fadd_rn(dot, dot));
                    const unsigned long long key =
                        ((unsigned long long)__float_as_uint(dd) << 32) | (unsigned int)k;
                    if (key < nb) nb = key;
                }
            }
            keys[p] = nb;
        } else {
            keys[p] = best;
        }
    }
    __syncthreads();

    // --- cooperative full exact scan for flagged points (all 256 threads) ---
    {
        const int nflag = *flag_cnt;
        for (int f = 0; f < nflag; ++f) {
            const int p = flag_list[f];
            const float znp = zn_s[p];
            unsigned long long nb = 0xFFFFFFFFFFFFFFFFull;
#pragma unroll
            for (int q = 0; q < 4; ++q) {
                const int k = tid * 4 + q;
                float dot = 0.0f;
#pragma unroll
                for (int c = 0; c < CDIM; ++c)
                    dot = __fmaf_rn(zs[c * ZSTR + p], emb[(size_t)k * CDIM + c], dot);
                const float dd = __fsub_rn(__fadd_rn(znp, en_s[k]), __fadd_rn(dot, dot));
                const unsigned long long key =
                    ((unsigned long long)__float_as_uint(dd) << 32) | (unsigned int)k;
                if (key < nb) nb = key;
            }
            atomicMin(&keys[p], nb);    // commutative min -> deterministic
        }
    }
    __syncthreads();

    // --- gather + straight-through output + loss partials ---
    double acc = 0.0;
    {
        const int p   = tid & 127;
        const int ch2 = tid >> 7;
        const int idx = (int)(keys[p] & 0xFFFFFFFFull);
        const float* erow = emb + (size_t)idx * CDIM + ch2 * 32;
        const size_t obase = zb + hw0 + p;
#pragma unroll
        for (int c4 = 0; c4 < 8; ++c4) {
            const float4 e4 = *(const float4*)&erow[c4 * 4];
            const float ee[4] = {e4.x, e4.y, e4.z, e4.w};
#pragma unroll
            for (int q = 0; q < 4; ++q) {
                const int c = ch2 * 32 + c4 * 4 + q;
                const size_t off = obase + (size_t)c * HW;
                const float zv = zs[c * ZSTR + p];
                const float dd = __fsub_rn(ee[q], zv);
                out[off] = __fadd_rn(zv, dd);            // fl(z + (z_q - z))
                acc += (double)__fmul_rn(dd, dd);
            }
        }
    }
    __syncthreads();    // flag area reuse ended; now safe to write red

    red[tid] = acc;
    __syncthreads();
#pragma unroll
    for (int s = 128; s >= 1; s >>= 1) {
        if (tid < s) red[tid] += red[tid + s];
        __syncthreads();
    }
    if (tid == 0) g_part[blockIdx.x] = red[0];
}

// ---------------------------------------------------------------------------
__global__ void loss_kernel(float* __restrict__ out, int out_size) {
    __shared__ double red[256];
    const int tid = threadIdx.x;
    red[tid] = g_part[tid] + g_part[tid + 256] + g_part[tid + 512] + g_part[tid + 768];
    __syncthreads();
#pragma unroll
    for (int s = 128; s >= 1; s >>= 1) {
        if (tid < s) red[tid] += red[tid + s];
        __syncthreads();
    }
    if (tid == 0) {
        const double mean = red[0] / (double)ZQ_ELEMS;
        const float mf = (float)mean;
        out[out_size - 1] = __fadd_rn(mf, __fmul_rn(0.5f, mf));
    }
}

// ---------------------------------------------------------------------------
extern "C" void kernel_launch(void* const* d_in, const int* in_sizes, int n_in,
                              void* d_out, int out_size) {
    const float* z   = (const float*)d_in[0];
    const float* emb = (const float*)d_in[1];
    float* out = (float*)d_out;

    cudaFuncSetAttribute(vq_main_kernel,
                         cudaFuncAttributeMaxDynamicSharedMemorySize, SM_TOTAL);

    prep_kernel<<<4, 256>>>(emb);
    vq_main_kernel<<<NPTS / 128, 256, SM_TOTAL>>>(z, emb, out);
    loss_kernel<<<1, 256>>>(out, out_size);
}

// round 12
// speedup vs baseline: 5.4132x; 1.0134x over previous
#include <cuda_runtime.h>
#include <cuda_bf16.h>
#include <cstdint>

#define BATCH 32
#define CDIM  64
#define HW    4096
#define NPTS  (BATCH * HW)          // 131072
#define KCODES 1024
#define ZQ_ELEMS (NPTS * CDIM)      // 8388608
#define NCHUNK 128
#define BSTR   132                  // u64 stride; 132*8=1056 (16B-aligned), j-stride 264w = 8 mod 32 banks -> conflict-free
#define ZSTR   132                  // f32 stride for ZS rows
#define EPS_M  3e-5f                // window in m-space (= 6e-5 in d-space, validated)

// ---------------------------------------------------------------------------
// Device-global scratch (allocation-free rule)
// ---------------------------------------------------------------------------
__device__ float  g_enorm[KCODES];
__device__ double g_part[1024];
// Pre-packed B fragments: [row = kt*4+r][code n], u64 = {b0 = bf16x2(c0,c0+1),
// b1 = bf16x2(c0+8,c0+9)} with c0 = kt*16 + 2r.
__device__ unsigned long long g_ebh2[16 * KCODES];
__device__ unsigned long long g_ebl2[16 * KCODES];

// ---------------------------------------------------------------------------
__device__ __forceinline__ void mma16816(float* d, const uint32_t* a,
                                         uint32_t b0, uint32_t b1) {
    asm volatile(
        "mma.sync.aligned.m16n8k16.row.col.f32.bf16.bf16.f32 "
        "{%0,%1,%2,%3}, {%4,%5,%6,%7}, {%8,%9}, {%0,%1,%2,%3};"
        : "+f"(d[0]), "+f"(d[1]), "+f"(d[2]), "+f"(d[3])
        : "r"(a[0]), "r"(a[1]), "r"(a[2]), "r"(a[3]), "r"(b0), "r"(b1));
}

__device__ __forceinline__ uint32_t pack_bf16x2(float lo, float hi) {
    const uint16_t l = __bfloat16_as_ushort(__float2bfloat16_rn(lo));
    const uint16_t h = __bfloat16_as_ushort(__float2bfloat16_rn(hi));
    return ((uint32_t)h << 16) | l;
}

__device__ __forceinline__ uint32_t smem_u32(const void* p) {
    uint32_t a;
    asm("{ .reg .u64 t; cvta.to.shared.u64 t, %1; cvt.u32.u64 %0, t; }"
        : "=r"(a) : "l"(p));
    return a;
}

#define CP_ASYNC16(dst_u32, src_ptr)                                           \
    asm volatile("cp.async.cg.shared.global [%0], [%1], 16;"                   \
                 :: "r"(dst_u32), "l"(src_ptr) : "memory")
#define CP_COMMIT()  asm volatile("cp.async.commit_group;" ::: "memory")
#define CP_WAIT1()   asm volatile("cp.async.wait_group 1;" ::: "memory")
#define CP_WAIT0()   asm volatile("cp.async.wait_group 0;" ::: "memory")

// ---------------------------------------------------------------------------
// SMEM layout (bytes)
// ---------------------------------------------------------------------------
#define BTERM    16896                        // 16 rows * BSTR * 8 bytes per term
#define SM_ZN    0                            // 128 f32            (512)
#define SM_KEYS  512                          // 128 u64            (1024)
#define SM_RED   1536                         // 256 double (2048); also flags
#define SM_EN    3584                         // 1024 f32 enh'=2+en/2 (4096)
#define SM_ZS    7680                         // f32[64][ZSTR]      (33792)
#define SM_B0    41472                        // chunk buf 0: hi + lo (33792)
#define SM_B1    75264                        // chunk buf 1 (33792)
#define SM_TOP   SM_B0                        // u64[128][4][2] aliased into B0
#define SM_TOTAL 109056                       // 106.5 KB (2 CTAs/SM on 228KB)

// ---------------------------------------------------------------------------
// Kernel 0: emb prep — enorm + packed bf16 hi/lo B-fragment images
// ---------------------------------------------------------------------------
__global__ void prep_kernel(const float* __restrict__ emb) {
    const int n = blockIdx.x * 256 + threadIdx.x;
    if (n >= KCODES) return;
    float acc = 0.0f;
#pragma unroll
    for (int kt = 0; kt < 4; ++kt) {
        float e[16];
#pragma unroll
        for (int i = 0; i < 4; ++i) {
            const float4 v = *(const float4*)&emb[(size_t)n * CDIM + kt * 16 + i * 4];
            e[i * 4 + 0] = v.x; e[i * 4 + 1] = v.y;
            e[i * 4 + 2] = v.z; e[i * 4 + 3] = v.w;
        }
#pragma unroll
        for (int i = 0; i < 16; ++i)
            acc = __fadd_rn(acc, __fmul_rn(e[i], e[i]));
        float eh[16], el[16];
#pragma unroll
        for (int i = 0; i < 16; ++i) {
            eh[i] = __bfloat162float(__float2bfloat16_rn(e[i]));
            el[i] = __fsub_rn(e[i], eh[i]);
        }
#pragma unroll
        for (int r = 0; r < 4; ++r) {
            const int c0 = 2 * r;
            const int row = kt * 4 + r;
            unsigned long long vh =
                ((unsigned long long)pack_bf16x2(eh[c0 + 8], eh[c0 + 9]) << 32) |
                pack_bf16x2(eh[c0], eh[c0 + 1]);
            unsigned long long vl =
                ((unsigned long long)pack_bf16x2(el[c0 + 8], el[c0 + 9]) << 32) |
                pack_bf16x2(el[c0], el[c0 + 1]);
            g_ebh2[row * KCODES + n] = vh;
            g_ebl2[row * KCODES + n] = vl;
        }
    }
    g_enorm[n] = acc;
}

// ---------------------------------------------------------------------------
// Kernel 1: mma.sync GEMM scan + exact-rescue argmin + gather + loss
// ---------------------------------------------------------------------------
__global__ __launch_bounds__(256, 2)
void vq_main_kernel(const float* __restrict__ z, const float* __restrict__ emb,
                    float* __restrict__ out) {
    extern __shared__ char smem[];
    float*  zn_s  = (float*)(smem + SM_ZN);
    unsigned long long* keys = (unsigned long long*)(smem + SM_KEYS);
    double* red   = (double*)(smem + SM_RED);
    int*    flag_cnt  = (int*)(smem + SM_RED);
    int*    flag_list = (int*)(smem + SM_RED + 4);
    float*  en_s  = (float*)(smem + SM_EN);        // enh' = 2 + en/2
    unsigned long long* top = (unsigned long long*)(smem + SM_TOP);
    float*  zs    = (float*)(smem + SM_ZS);

    const uint32_t sb = smem_u32(smem);
    const int tid  = threadIdx.x;
    const int wid  = tid >> 5;
    const int lane = tid & 31;
    const int g    = lane >> 2;
    const int j    = lane & 3;

    const int m0  = blockIdx.x * 128;
    const int b   = m0 >> 12;
    const int hw0 = m0 & 4095;
    const size_t zb = (size_t)b * (CDIM * HW);

    if (tid == 0) *flag_cnt = 0;

    // --- prefetch B chunk 0 via cp.async (overlaps with staging below) ---
    const uint32_t bufofs[2] = {SM_B0, SM_B1};
    {
#pragma unroll
        for (int q = 0; q < 8; ++q) {
            const int idx = q * 256 + tid;          // 0..2047 16B-jobs
            const int term = idx >> 10;
            const int rem  = idx & 1023;
            const int row  = rem >> 6;
            const int seg  = rem & 63;
            const unsigned long long* src =
                (term ? g_ebl2 : g_ebh2) + row * KCODES + seg * 2;
            const uint32_t dst = sb + SM_B0 + term * BTERM +
                                 row * (BSTR * 8) + seg * 16;
            CP_ASYNC16(dst, src);
        }
        CP_COMMIT();
    }

    // --- Stage exact z tile into ZS [c][p] ---
#pragma unroll
    for (int p8 = 0; p8 < 8; ++p8) {
        const int idx = p8 * 256 + tid;
        const int c  = idx >> 5;
        const int g4 = idx & 31;
        const float4 v = *(const float4*)&z[zb + (size_t)c * HW + hw0 + g4 * 4];
        *(float4*)&zs[c * ZSTR + g4 * 4] = v;
    }
    __syncthreads();

    // --- znorm (exact sequential) / enh' copy ---
    if (tid < 128) {
        float acc = 0.0f;
#pragma unroll
        for (int c = 0; c < CDIM; ++c) {
            const float v = zs[c * ZSTR + tid];
            acc = __fadd_rn(acc, __fmul_rn(v, v));
        }
        zn_s[tid] = acc;
    } else {
        const int i = tid - 128;
#pragma unroll
        for (int q = 0; q < 2; ++q) {
            const float4 v = ((const float4*)g_enorm)[i + q * 128];
            float4 o;
            o.x = __fadd_rn(2.0f, 0.5f * v.x);
            o.y = __fadd_rn(2.0f, 0.5f * v.y);
            o.z = __fadd_rn(2.0f, 0.5f * v.z);
            o.w = __fadd_rn(2.0f, 0.5f * v.w);
            ((float4*)en_s)[i + q * 128] = o;
        }
    }
    __syncthreads();

    // --- Build persistent A fragments from ZS ---
    const int p0 = wid * 16 + g;
    const int p1 = p0 + 8;
    uint32_t Ah[4][4], Al[4][4];
#pragma unroll
    for (int kt = 0; kt < 4; ++kt) {
        const int cA = kt * 16 + 2 * j;
        const int cB = cA + 8;
#pragma unroll
        for (int r = 0; r < 4; ++r) {
            const int cc = (r < 2) ? cA : cB;
            const int pp = (r & 1) ? p1 : p0;
            const float x0 = zs[cc * ZSTR + pp];
            const float x1 = zs[(cc + 1) * ZSTR + pp];
            const float h0 = __bfloat162float(__float2bfloat16_rn(x0));
            const float h1 = __bfloat162float(__float2bfloat16_rn(x1));
            Ah[kt][r] = pack_bf16x2(h0, h1);
            Al[kt][r] = pack_bf16x2(__fsub_rn(x0, h0), __fsub_rn(x1, h1));
        }
    }

    // per-lane top-2 of m-bits for each of the thread's two point rows
    uint32_t b0d0 = 0xFFFFFFFFu, b1d0 = 0xFFFFFFFFu;
    uint32_t b0d1 = 0xFFFFFFFFu, b1d1 = 0xFFFFFFFFu;
    int b0i0 = 0, b1i0 = 0, b0i1 = 0, b1i1 = 0;

    for (int ch = 0; ch < 8; ++ch) {
        __syncthreads();    // all warps done reading buf (ch-1)&1

        if (ch + 1 < 8) {   // prefetch next chunk into buf (ch+1)&1
            const int buf = (ch + 1) & 1;
#pragma unroll
            for (int q = 0; q < 8; ++q) {
                const int idx = q * 256 + tid;
                const int term = idx >> 10;
                const int rem  = idx & 1023;
                const int row  = rem >> 6;
                const int seg  = rem & 63;
                const unsigned long long* src =
                    (term ? g_ebl2 : g_ebh2) + row * KCODES + (ch + 1) * NCHUNK + seg * 2;
                const uint32_t dst = sb + bufofs[buf] + term * BTERM +
                                     row * (BSTR * 8) + seg * 16;
                CP_ASYNC16(dst, src);
            }
            CP_COMMIT();
            CP_WAIT1();     // chunk ch complete (ch+1 still in flight)
        } else {
            CP_WAIT0();
        }
        __syncthreads();    // chunk ch visible to all warps

        const uint2* bh = (const uint2*)(smem + bufofs[ch & 1]);
        const uint2* bl = (const uint2*)(smem + bufofs[ch & 1] + BTERM);

        for (int nt = 0; nt < 16; nt += 2) {
            float D[6][4];
#pragma unroll
            for (int i = 0; i < 6; ++i)
#pragma unroll
                for (int q = 0; q < 4; ++q) D[i][q] = 0.0f;

            const int n0 = nt * 8 + g;
            const int n1 = n0 + 8;
#pragma unroll
            for (int kt = 0; kt < 4; ++kt) {
                const int rb = (kt * 4 + j) * BSTR;
                const uint2 vh0 = bh[rb + n0];
                const uint2 vh1 = bh[rb + n1];
                const uint2 vl0 = bl[rb + n0];
                const uint2 vl1 = bl[rb + n1];
                mma16816(D[0], Ah[kt], vh0.x, vh0.y);
                mma16816(D[1], Ah[kt], vh1.x, vh1.y);
                mma16816(D[2], Al[kt], vh0.x, vh0.y);
                mma16816(D[3], Al[kt], vh1.x, vh1.y);
                mma16816(D[4], Ah[kt], vl0.x, vl0.y);
                mma16816(D[5], Ah[kt], vl1.x, vl1.y);
            }

#pragma unroll
            for (int t = 0; t < 2; ++t) {
                const int kb = ch * 128 + (nt + t) * 8 + 2 * j;
                const float2 en2 = *(const float2*)&en_s[kb];   // enh'
                float dot[4];
#pragma unroll
                for (int q = 0; q < 4; ++q)
                    dot[q] = __fadd_rn(__fadd_rn(D[t][q], D[2 + t][q]), D[4 + t][q]);

                // m = enh' - dot  (positive, ~2.0; ordering == d ordering)
                const float m00 = __fsub_rn(en2.x, dot[0]);
                const float m01 = __fsub_rn(en2.y, dot[1]);
                const float m10 = __fsub_rn(en2.x, dot[2]);
                const float m11 = __fsub_rn(en2.y, dot[3]);

#define UPD(dv, ki, B0D, B0I, B1D, B1I)                                        \
                { const uint32_t u = __float_as_uint(dv);                      \
                  if (u < B0D) { B1D = B0D; B1I = B0I; B0D = u; B0I = (ki); }  \
                  else if (u < B1D) { B1D = u; B1I = (ki); } }

                UPD(m00, kb,     b0d0, b0i0, b1d0, b1i0);
                UPD(m01, kb + 1, b0d0, b0i0, b1d0, b1i0);
                UPD(m10, kb,     b0d1, b0i1, b1d1, b1i1);
                UPD(m11, kb + 1, b0d1, b0i1, b1d1, b1i1);
#undef UPD
            }
        }
    }
    __syncthreads();   // B buffers dead -> safe to alias TOP

    // --- publish per-lane top-2 ---
    top[(p0 * 4 + j) * 2 + 0] = ((unsigned long long)b0d0 << 32) | (unsigned int)b0i0;
    top[(p0 * 4 + j) * 2 + 1] = ((unsigned long long)b1d0 << 32) | (unsigned int)b1i0;
    top[(p1 * 4 + j) * 2 + 0] = ((unsigned long long)b0d1 << 32) | (unsigned int)b0i1;
    top[(p1 * 4 + j) * 2 + 1] = ((unsigned long long)b1d1 << 32) | (unsigned int)b1i1;
    __syncthreads();

    // --- rescue decision (m-space window; exact fp32 re-check if ambiguous) ---
    if (tid < 128) {
        const int p = tid;
        unsigned long long kk[8];
#pragma unroll
        for (int l = 0; l < 4; ++l) {
            kk[2 * l]     = top[(p * 4 + l) * 2];
            kk[2 * l + 1] = top[(p * 4 + l) * 2 + 1];
        }
        unsigned long long best = kk[0];
#pragma unroll
        for (int i = 1; i < 8; ++i) if (kk[i] < best) best = kk[i];

        const float bm  = __uint_as_float((uint32_t)(best >> 32));
        const float thr = __fadd_rn(bm, EPS_M);

        bool full = false, need = false;
#pragma unroll
        for (int l = 0; l < 4; ++l) {
            const float m2 = __uint_as_float((uint32_t)(kk[2 * l + 1] >> 32));
            if (m2 <= thr) full = true;
        }
#pragma unroll
        for (int i = 0; i < 8; ++i) {
            const float mi = __uint_as_float((uint32_t)(kk[i] >> 32));
            if (kk[i] != best && mi <= thr) need = true;
        }

        if (full) {
            keys[p] = 0xFFFFFFFFFFFFFFFFull;
            const int slot = atomicAdd(flag_cnt, 1);
            flag_list[slot] = p;
        } else if (need) {
            const float znp = zn_s[p];
            unsigned long long nb = 0xFFFFFFFFFFFFFFFFull;
#pragma unroll
            for (int i = 0; i < 8; ++i) {
                const float mi = __uint_as_float((uint32_t)(kk[i] >> 32));
                if (mi <= thr) {
                    const int k = (int)(kk[i] & 0xFFFFFFFFull);
                    float dot = 0.0f;
#pragma unroll
                    for (int c = 0; c < CDIM; ++c)
                        dot = __fmaf_rn(zs[c * ZSTR + p], emb[(size_t)k * CDIM + c], dot);
                    const float dd = __fsub_rn(__fadd_rn(znp, g_enorm[k]),
                                               __fadd_rn(dot, dot));
                    const unsigned long long key =
                        ((unsigned long long)__float_as_uint(dd) << 32) | (unsigned int)k;
                    if (key < nb) nb = key;
                }
            }
            keys[p] = nb;
        } else {
            keys[p] = best;   // low 32 bits = index (only part consumed)
        }
    }
    __syncthreads();

    // --- cooperative full exact scan for flagged points (all 256 threads) ---
    {
        const int nflag = *flag_cnt;
        for (int f = 0; f < nflag; ++f) {
            const int p = flag_list[f];
            const float znp = zn_s[p];
            unsigned long long nb = 0xFFFFFFFFFFFFFFFFull;
#pragma unroll
            for (int q = 0; q < 4; ++q) {
                const int k = tid * 4 + q;
                float dot = 0.0f;
#pragma unroll
                for (int c = 0; c < CDIM; ++c)
                    dot = __fmaf_rn(zs[c * ZSTR + p], emb[(size_t)k * CDIM + c], dot);
                const float dd = __fsub_rn(__fadd_rn(znp, g_enorm[k]),
                                           __fadd_rn(dot, dot));
                const unsigned long long key =
                    ((unsigned long long)__float_as_uint(dd) << 32) | (unsigned int)k;
                if (key < nb) nb = key;
            }
            atomicMin(&keys[p], nb);
        }
    }
    __syncthreads();

    // --- gather + straight-through output + loss partials ---
    double acc = 0.0;
    {
        const int p   = tid & 127;
        const int ch2 = tid >> 7;
        const int idx = (int)(keys[p] & 0xFFFFFFFFull);
        const float* erow = emb + (size_t)idx * CDIM + ch2 * 32;
        const size_t obase = zb + hw0 + p;
#pragma unroll
        for (int c4 = 0; c4 < 8; ++c4) {
            const float4 e4 = *(const float4*)&erow[c4 * 4];
            const float ee[4] = {e4.x, e4.y, e4.z, e4.w};
#pragma unroll
            for (int q = 0; q < 4; ++q) {
                const int c = ch2 * 32 + c4 * 4 + q;
                const size_t off = obase + (size_t)c * HW;
                const float zv = zs[c * ZSTR + p];
                const float dd = __fsub_rn(ee[q], zv);
                out[off] = __fadd_rn(zv, dd);            // fl(z + (z_q - z))
                acc += (double)__fmul_rn(dd, dd);
            }
        }
    }
    __syncthreads();

    red[tid] = acc;
    __syncthreads();
#pragma unroll
    for (int s = 128; s >= 1; s >>= 1) {
        if (tid < s) red[tid] += red[tid + s];
        __syncthreads();
    }
    if (tid == 0) g_part[blockIdx.x] = red[0];
}

// ---------------------------------------------------------------------------
__global__ void loss_kernel(float* __restrict__ out, int out_size) {
    __shared__ double red[256];
    const int tid = threadIdx.x;
    red[tid] = g_part[tid] + g_part[tid + 256] + g_part[tid + 512] + g_part[tid + 768];
    __syncthreads();
#pragma unroll
    for (int s = 128; s >= 1; s >>= 1) {
        if (tid < s) red[tid] += red[tid + s];
        __syncthreads();
    }
    if (tid == 0) {
        const double mean = red[0] / (double)ZQ_ELEMS;
        const float mf = (float)mean;
        out[out_size - 1] = __fadd_rn(mf, __fmul_rn(0.5f, mf));
    }
}

// ---------------------------------------------------------------------------
extern "C" void kernel_launch(void* const* d_in, const int* in_sizes, int n_in,
                              void* d_out, int out_size) {
    const float* z   = (const float*)d_in[0];
    const float* emb = (const float*)d_in[1];
    float* out = (float*)d_out;

    cudaFuncSetAttribute(vq_main_kernel,
                         cudaFuncAttributeMaxDynamicSharedMemorySize, SM_TOTAL);

    prep_kernel<<<4, 256>>>(emb);
    vq_main_kernel<<<NPTS / 128, 256, SM_TOTAL>>>(z, emb, out);
    loss_kernel<<<1, 256>>>(out, out_size);
}

// round 15
// speedup vs baseline: 6.1264x; 1.1317x over previous
#include <cuda_runtime.h>
#include <cuda_fp16.h>
#include <cstdint>

#define BATCH 32
#define CDIM  64
#define HW    4096
#define NPTS  (BATCH * HW)          // 131072
#define KCODES 1024
#define ZQ_ELEMS (NPTS * CDIM)      // 8388608
#define NCHUNK 128
#define BSTR   132                  // u64 stride; 1056B rows (16B-aligned), conflict-free
#define ZSTR   132                  // f32 stride for ZS rows

// ---------------------------------------------------------------------------
// Device-global scratch (allocation-free rule)
// ---------------------------------------------------------------------------
__device__ float  g_enorm[KCODES];
__device__ double g_part[1024];
__device__ int    g_elmax_bits;     // max_k ||e_k - fp16(e_k)||  (float bits)
// Pre-packed fp16 B fragments (hi term only): [row = kt*4+r][code n],
// u64 = {b0 = half2(c0,c0+1), b1 = half2(c0+8,c0+9)} with c0 = kt*16 + 2r.
__device__ unsigned long long g_ebh2[16 * KCODES];

// ---------------------------------------------------------------------------
__device__ __forceinline__ void mma16816(float* d, const uint32_t* a,
                                         uint32_t b0, uint32_t b1) {
    asm volatile(
        "mma.sync.aligned.m16n8k16.row.col.f32.f16.f16.f32 "
        "{%0,%1,%2,%3}, {%4,%5,%6,%7}, {%8,%9}, {%0,%1,%2,%3};"
        : "+f"(d[0]), "+f"(d[1]), "+f"(d[2]), "+f"(d[3])
        : "r"(a[0]), "r"(a[1]), "r"(a[2]), "r"(a[3]), "r"(b0), "r"(b1));
}

__device__ __forceinline__ uint32_t pack_h2(float lo, float hi) {
    const uint16_t l = __half_as_ushort(__float2half_rn(lo));
    const uint16_t h = __half_as_ushort(__float2half_rn(hi));
    return ((uint32_t)h << 16) | l;
}

__device__ __forceinline__ uint32_t smem_u32(const void* p) {
    uint32_t a;
    asm("{ .reg .u64 t; cvta.to.shared.u64 t, %1; cvt.u32.u64 %0, t; }"
        : "=r"(a) : "l"(p));
    return a;
}

#define CP_ASYNC16(dst_u32, src_ptr)                                           \
    asm volatile("cp.async.cg.shared.global [%0], [%1], 16;"                   \
                 :: "r"(dst_u32), "l"(src_ptr) : "memory")
#define CP_COMMIT()  asm volatile("cp.async.commit_group;" ::: "memory")
#define CP_WAIT1()   asm volatile("cp.async.wait_group 1;" ::: "memory")
#define CP_WAIT0()   asm volatile("cp.async.wait_group 0;" ::: "memory")

// ---------------------------------------------------------------------------
// SMEM layout (bytes)
// ---------------------------------------------------------------------------
#define BTERM    16896                        // 16 rows * BSTR * 8 bytes (hi only)
#define SM_ZN    0                            // 128 f32            (512)
#define SM_KEYS  512                          // 128 u64            (1024)
#define SM_RED   1536                         // 256 double (2048); also flags
#define SM_EN    3584                         // 1024 f32 enh'=2+en/2 (4096)
#define SM_ZS    7680                         // f32[64][ZSTR]      (33792)
#define SM_B0    41472                        // chunk buf 0 (16896)
#define SM_B1    58368                        // chunk buf 1 (16896)
#define SM_TOP   SM_B0                        // u64[128][4][2] aliased into B0
#define SM_TOTAL 75264                        // 73.5 KB

// ---------------------------------------------------------------------------
// Kernel 0: emb prep — enorm + fp16 B fragments + exact elmax bound
// ---------------------------------------------------------------------------
__global__ void prep_kernel(const float* __restrict__ emb) {
    const int n = blockIdx.x * 256 + threadIdx.x;
    if (n >= KCODES) return;
    float acc = 0.0f;
    float eln2 = 0.0f;
#pragma unroll
    for (int kt = 0; kt < 4; ++kt) {
        float e[16];
#pragma unroll
        for (int i = 0; i < 4; ++i) {
            const float4 v = *(const float4*)&emb[(size_t)n * CDIM + kt * 16 + i * 4];
            e[i * 4 + 0] = v.x; e[i * 4 + 1] = v.y;
            e[i * 4 + 2] = v.z; e[i * 4 + 3] = v.w;
        }
        float eh[16];
#pragma unroll
        for (int i = 0; i < 16; ++i) {
            acc = __fadd_rn(acc, __fmul_rn(e[i], e[i]));
            eh[i] = __half2float(__float2half_rn(e[i]));
            const float el = __fsub_rn(e[i], eh[i]);
            eln2 = __fmaf_rn(el, el, eln2);
        }
#pragma unroll
        for (int r = 0; r < 4; ++r) {
            const int c0 = 2 * r;
            const int row = kt * 4 + r;
            const unsigned long long vh =
                ((unsigned long long)pack_h2(eh[c0 + 8], eh[c0 + 9]) << 32) |
                pack_h2(eh[c0], eh[c0 + 1]);
            g_ebh2[row * KCODES + n] = vh;
        }
    }
    g_enorm[n] = acc;
    atomicMax(&g_elmax_bits, __float_as_int(sqrtf(eln2)));  // positive floats
}

// ---------------------------------------------------------------------------
// Kernel 1: fp16 2-term mma.sync GEMM scan + exact-rescue argmin + gather + loss
// ---------------------------------------------------------------------------
__global__ __launch_bounds__(256, 2)
void vq_main_kernel(const float* __restrict__ z, const float* __restrict__ emb,
                    float* __restrict__ out) {
    extern __shared__ char smem[];
    float*  zn_s  = (float*)(smem + SM_ZN);
    unsigned long long* keys = (unsigned long long*)(smem + SM_KEYS);
    double* red   = (double*)(smem + SM_RED);
    int*    flag_cnt  = (int*)(smem + SM_RED);
    int*    flag_list = (int*)(smem + SM_RED + 4);
    float*  en_s  = (float*)(smem + SM_EN);        // enh' = 2 + en/2
    unsigned long long* top = (unsigned long long*)(smem + SM_TOP);
    float*  zs    = (float*)(smem + SM_ZS);

    const uint32_t sb = smem_u32(smem);
    const int tid  = threadIdx.x;
    const int wid  = tid >> 5;
    const int lane = tid & 31;
    const int g    = lane >> 2;
    const int j    = lane & 3;

    const int m0  = blockIdx.x * 128;
    const int b   = m0 >> 12;
    const int hw0 = m0 & 4095;
    const size_t zb = (size_t)b * (CDIM * HW);

    if (tid == 0) *flag_cnt = 0;

    // --- prefetch B chunk 0 via cp.async ---
    const uint32_t bufofs[2] = {SM_B0, SM_B1};
    {
#pragma unroll
        for (int q = 0; q < 4; ++q) {
            const int idx = q * 256 + tid;          // 0..1023 16B-jobs
            const int row = idx >> 6;
            const int seg = idx & 63;
            const unsigned long long* src = g_ebh2 + row * KCODES + seg * 2;
            const uint32_t dst = sb + SM_B0 + row * (BSTR * 8) + seg * 16;
            CP_ASYNC16(dst, src);
        }
        CP_COMMIT();
    }

    // --- Stage exact z tile into ZS [c][p] ---
#pragma unroll
    for (int p8 = 0; p8 < 8; ++p8) {
        const int idx = p8 * 256 + tid;
        const int c  = idx >> 5;
        const int g4 = idx & 31;
        const float4 v = *(const float4*)&z[zb + (size_t)c * HW + hw0 + g4 * 4];
        *(float4*)&zs[c * ZSTR + g4 * 4] = v;
    }
    __syncthreads();

    // --- znorm (exact sequential) / enh' copy ---
    if (tid < 128) {
        float acc = 0.0f;
#pragma unroll
        for (int c = 0; c < CDIM; ++c) {
            const float v = zs[c * ZSTR + tid];
            acc = __fadd_rn(acc, __fmul_rn(v, v));
        }
        zn_s[tid] = acc;
    } else {
        const int i = tid - 128;
#pragma unroll
        for (int q = 0; q < 2; ++q) {
            const float4 v = ((const float4*)g_enorm)[i + q * 128];
            float4 o;
            o.x = __fadd_rn(2.0f, 0.5f * v.x);
            o.y = __fadd_rn(2.0f, 0.5f * v.y);
            o.z = __fadd_rn(2.0f, 0.5f * v.z);
            o.w = __fadd_rn(2.0f, 0.5f * v.w);
            ((float4*)en_s)[i + q * 128] = o;
        }
    }
    __syncthreads();

    // --- Build persistent fp16 A fragments (hi + lo) from ZS ---
    const int p0 = wid * 16 + g;
    const int p1 = p0 + 8;
    uint32_t Ah[4][4], Al[4][4];
#pragma unroll
    for (int kt = 0; kt < 4; ++kt) {
        const int cA = kt * 16 + 2 * j;
        const int cB = cA + 8;
#pragma unroll
        for (int r = 0; r < 4; ++r) {
            const int cc = (r < 2) ? cA : cB;
            const int pp = (r & 1) ? p1 : p0;
            const float x0 = zs[cc * ZSTR + pp];
            const float x1 = zs[(cc + 1) * ZSTR + pp];
            const float h0 = __half2float(__float2half_rn(x0));
            const float h1 = __half2float(__float2half_rn(x1));
            Ah[kt][r] = pack_h2(h0, h1);
            Al[kt][r] = pack_h2(__fsub_rn(x0, h0), __fsub_rn(x1, h1));
        }
    }

    // per-lane top-2 of m-bits for each of the thread's two point rows
    uint32_t b0d0 = 0xFFFFFFFFu, b1d0 = 0xFFFFFFFFu;
    uint32_t b0d1 = 0xFFFFFFFFu, b1d1 = 0xFFFFFFFFu;
    int b0i0 = 0, b1i0 = 0, b0i1 = 0, b1i1 = 0;

    for (int ch = 0; ch < 8; ++ch) {
        __syncthreads();    // all warps done reading buf (ch-1)&1

        if (ch + 1 < 8) {   // prefetch next chunk into buf (ch+1)&1
            const int buf = (ch + 1) & 1;
#pragma unroll
            for (int q = 0; q < 4; ++q) {
                const int idx = q * 256 + tid;
                const int row = idx >> 6;
                const int seg = idx & 63;
                const unsigned long long* src =
                    g_ebh2 + row * KCODES + (ch + 1) * NCHUNK + seg * 2;
                const uint32_t dst = sb + bufofs[buf] + row * (BSTR * 8) + seg * 16;
                CP_ASYNC16(dst, src);
            }
            CP_COMMIT();
            CP_WAIT1();     // chunk ch complete
        } else {
            CP_WAIT0();
        }
        __syncthreads();

        const uint2* bh = (const uint2*)(smem + bufofs[ch & 1]);

        for (int nt = 0; nt < 16; nt += 2) {
            float D[4][4];
#pragma unroll
            for (int i = 0; i < 4; ++i)
#pragma unroll
                for (int q = 0; q < 4; ++q) D[i][q] = 0.0f;

            const int n0 = nt * 8 + g;
            const int n1 = n0 + 8;
#pragma unroll
            for (int kt = 0; kt < 4; ++kt) {
                const int rb = (kt * 4 + j) * BSTR;
                const uint2 vh0 = bh[rb + n0];
                const uint2 vh1 = bh[rb + n1];
                mma16816(D[0], Ah[kt], vh0.x, vh0.y);
                mma16816(D[1], Ah[kt], vh1.x, vh1.y);
                mma16816(D[2], Al[kt], vh0.x, vh0.y);
                mma16816(D[3], Al[kt], vh1.x, vh1.y);
            }

#pragma unroll
            for (int t = 0; t < 2; ++t) {
                const int kb = ch * 128 + (nt + t) * 8 + 2 * j;
                const float2 en2 = *(const float2*)&en_s[kb];   // enh'
                float dot[4];
#pragma unroll
                for (int q = 0; q < 4; ++q)
                    dot[q] = __fadd_rn(D[t][q], D[2 + t][q]);

                // m = enh' - dot  (positive, ~2.0; ordering == d ordering)
                const float m00 = __fsub_rn(en2.x, dot[0]);
                const float m01 = __fsub_rn(en2.y, dot[1]);
                const float m10 = __fsub_rn(en2.x, dot[2]);
                const float m11 = __fsub_rn(en2.y, dot[3]);

#define UPD(dv, ki, B0D, B0I, B1D, B1I)                                        \
                { const uint32_t u = __float_as_uint(dv);                      \
                  if (u < B0D) { B1D = B0D; B1I = B0I; B0D = u; B0I = (ki); }  \
                  else if (u < B1D) { B1D = u; B1I = (ki); } }

                UPD(m00, kb,     b0d0, b0i0, b1d0, b1i0);
                UPD(m01, kb + 1, b0d0, b0i0, b1d0, b1i0);
                UPD(m10, kb,     b0d1, b0i1, b1d1, b1i1);
                UPD(m11, kb + 1, b0d1, b0i1, b1d1, b1i1);
#undef UPD
            }
        }
    }
    __syncthreads();   // B buffers dead -> safe to alias TOP

    // --- publish per-lane top-2 ---
    top[(p0 * 4 + j) * 2 + 0] = ((unsigned long long)b0d0 << 32) | (unsigned int)b0i0;
    top[(p0 * 4 + j) * 2 + 1] = ((unsigned long long)b1d0 << 32) | (unsigned int)b1i0;
    top[(p1 * 4 + j) * 2 + 0] = ((unsigned long long)b0d1 << 32) | (unsigned int)b0i1;
    top[(p1 * 4 + j) * 2 + 1] = ((unsigned long long)b1d1 << 32) | (unsigned int)b1i1;
    __syncthreads();

    // --- rescue decision (per-point adaptive window, exact fp32 re-check) ---
    if (tid < 128) {
        const int p = tid;
        unsigned long long kk[8];
#pragma unroll
        for (int l = 0; l < 4; ++l) {
            kk[2 * l]     = top[(p * 4 + l) * 2];
            kk[2 * l + 1] = top[(p * 4 + l) * 2 + 1];
        }
        unsigned long long best = kk[0];
#pragma unroll
        for (int i = 1; i < 8; ++i) if (kk[i] < best) best = kk[i];

        const float znp = zn_s[p];
        const float elmax = __int_as_float(g_elmax_bits);
        // |dot_mma - dot_exact| <= ||z||*elmax + slack; window = 2x that in m
        const float eps_p = 2.0f * (__fmaf_rn(sqrtf(znp), elmax, 1e-5f));
        const float bm  = __uint_as_float((uint32_t)(best >> 32));
        const float thr = __fadd_rn(bm, eps_p);

        bool full = false, need = false;
#pragma unroll
        for (int l = 0; l < 4; ++l) {
            const float m2 = __uint_as_float((uint32_t)(kk[2 * l + 1] >> 32));
            if (m2 <= thr) full = true;
        }
#pragma unroll
        for (int i = 0; i < 8; ++i) {
            const float mi = __uint_as_float((uint32_t)(kk[i] >> 32));
            if (kk[i] != best && mi <= thr) need = true;
        }

        if (full) {
            keys[p] = 0xFFFFFFFFFFFFFFFFull;
            const int slot = atomicAdd(flag_cnt, 1);
            flag_list[slot] = p;
        } else if (need) {
            unsigned long long nb = 0xFFFFFFFFFFFFFFFFull;
#pragma unroll
            for (int i = 0; i < 8; ++i) {
                const float mi = __uint_as_float((uint32_t)(kk[i] >> 32));
                if (mi <= thr) {
                    const int k = (int)(kk[i] & 0xFFFFFFFFull);
                    float dot = 0.0f;
#pragma unroll
                    for (int c = 0; c < CDIM; ++c)
                        dot = __fmaf_rn(zs[c * ZSTR + p], emb[(size_t)k * CDIM + c], dot);
                    const float dd = __fsub_rn(__fadd_rn(znp, g_enorm[k]),
                                               __fadd_rn(dot, dot));
                    const unsigned long long key =
                        ((unsigned long long)__float_as_uint(dd) << 32) | (unsigned int)k;
                    if (key < nb) nb = key;
                }
            }
            keys[p] = nb;
        } else {
            keys[p] = best;   // low 32 bits = index (only part consumed)
        }
    }
    __syncthreads();

    // --- cooperative full exact scan for flagged points (all 256 threads) ---
    {
        const int nflag = *flag_cnt;
        for (int f = 0; f < nflag; ++f) {
            const int p = flag_list[f];
            const float znp = zn_s[p];
            unsigned long long nb = 0xFFFFFFFFFFFFFFFFull;
#pragma unroll
            for (int q = 0; q < 4; ++q) {
                const int k = tid * 4 + q;
                float dot = 0.0f;
#pragma unroll
                for (int c = 0; c < CDIM; ++c)
                    dot = __fmaf_rn(zs[c * ZSTR + p], emb[(size_t)k * CDIM + c], dot);
                const float dd = __fsub_rn(__fadd_rn(znp, g_enorm[k]),
                                           __fadd_rn(dot, dot));
                const unsigned long long key =
                    ((unsigned long long)__float_as_uint(dd) << 32) | (unsigned int)k;
                if (key < nb) nb = key;
            }
            atomicMin(&keys[p], nb);
        }
    }
    __syncthreads();

    // --- gather + straight-through output + loss partials ---
    double acc = 0.0;
    {
        const int p   = tid & 127;
        const int ch2 = tid >> 7;
        const int idx = (int)(keys[p] & 0xFFFFFFFFull);
        const float* erow = emb + (size_t)idx * CDIM + ch2 * 32;
        const size_t obase = zb + hw0 + p;
#pragma unroll
        for (int c4 = 0; c4 < 8; ++c4) {
            const float4 e4 = *(const float4*)&erow[c4 * 4];
            const float ee[4] = {e4.x, e4.y, e4.z, e4.w};
#pragma unroll
            for (int q = 0; q < 4; ++q) {
                const int c = ch2 * 32 + c4 * 4 + q;
                const size_t off = obase + (size_t)c * HW;
                const float zv = zs[c * ZSTR + p];
                const float dd = __fsub_rn(ee[q], zv);
                out[off] = __fadd_rn(zv, dd);            // fl(z + (z_q - z))
                acc += (double)__fmul_rn(dd, dd);
            }
        }
    }
    __syncthreads();

    red[tid] = acc;
    __syncthreads();
#pragma unroll
    for (int s = 128; s >= 1; s >>= 1) {
        if (tid < s) red[tid] += red[tid + s];
        __syncthreads();
    }
    if (tid == 0) g_part[blockIdx.x] = red[0];
}

// ---------------------------------------------------------------------------
__global__ void loss_kernel(float* __restrict__ out, int out_size) {
    __shared__ double red[256];
    const int tid = threadIdx.x;
    red[tid] = g_part[tid] + g_part[tid + 256] + g_part[tid + 512] + g_part[tid + 768];
    __syncthreads();
#pragma unroll
    for (int s = 128; s >= 1; s >>= 1) {
        if (tid < s) red[tid] += red[tid + s];
        __syncthreads();
    }
    if (tid == 0) {
        const double mean = red[0] / (double)ZQ_ELEMS;
        const float mf = (float)mean;
        out[out_size - 1] = __fadd_rn(mf, __fmul_rn(0.5f, mf));
    }
}

// ---------------------------------------------------------------------------
extern "C" void kernel_launch(void* const* d_in, const int* in_sizes, int n_in,
                              void* d_out, int out_size) {
    const float* z   = (const float*)d_in[0];
    const float* emb = (const float*)d_in[1];
    float* out = (float*)d_out;

    cudaFuncSetAttribute(vq_main_kernel,
                         cudaFuncAttributeMaxDynamicSharedMemorySize, SM_TOTAL);

    prep_kernel<<<4, 256>>>(emb);
    vq_main_kernel<<<NPTS / 128, 256, SM_TOTAL>>>(z, emb, out);
    loss_kernel<<<1, 256>>>(out, out_size);
}